// round 3
// baseline (speedup 1.0000x reference)
#include <cuda_runtime.h>

#define N_TOKENS  131072
#define CODE_DIM  64
#define NUM_CODES 1024

// ---------------- device scratch (no allocations allowed) ----------------
__device__ float g_counts[NUM_CODES];
__device__ float g_dw[NUM_CODES * CODE_DIM];
__device__ float g_loss;
__device__ float g_ncs[NUM_CODES];
__device__ float g_n;

// ---------------- zero scratch each launch (graph-capturable) ----------------
__global__ void vq_zero() {
    int i = blockIdx.x * blockDim.x + threadIdx.x;
    if (i < NUM_CODES * CODE_DIM) g_dw[i] = 0.0f;
    if (i < NUM_CODES) g_counts[i] = 0.0f;
    if (i == 0) g_loss = 0.0f;
}

// ---------------- main: distances + argmin + quantize + scatter stats ----------------
// Block: 128 tokens x all 1024 codes (8 tiles of 128 codes), K = 64 resident.
// 256 threads as 16x16, each owns an 8x8 (token x code) micro-tile.
__global__ __launch_bounds__(256, 2)
void vq_main(const float* __restrict__ z, const float* __restrict__ codebook,
             float* __restrict__ out_q, float* __restrict__ out_idx)
{
    extern __shared__ float smem[];
    float* zsT  = smem;                 // [64][128]  z tile, K-major
    float* csT  = zsT + 64 * 128;       // [64][128]  codebook tile, K-major
    float* zz_s = csT + 64 * 128;       // [128]      ||z_i||^2
    float* cc_s = zz_s + 128;           // [128]      ||c_k||^2 (current tile)
    float* red_d = cc_s + 128;          // [128][16]  per-tx best d2
    int*   red_i = (int*)(red_d + 128 * 16); // [128][16] per-tx best idx

    const int tid = threadIdx.x;
    const int tx = tid & 15;
    const int ty = tid >> 4;
    const int token0 = blockIdx.x * 128;

    // ---- load z tile transposed into smem + row sumsq ----
    {
        int r = tid >> 1, h = tid & 1;   // 2 threads per token row
        const float4* zp = reinterpret_cast<const float4*>(
            z + (size_t)(token0 + r) * CODE_DIM) + h * 8;
        float sq = 0.0f;
        #pragma unroll
        for (int v = 0; v < 8; v++) {
            float4 t = zp[v];
            int k = h * 32 + v * 4;
            zsT[(k + 0) * 128 + r] = t.x;
            zsT[(k + 1) * 128 + r] = t.y;
            zsT[(k + 2) * 128 + r] = t.z;
            zsT[(k + 3) * 128 + r] = t.w;
            sq += t.x * t.x; sq += t.y * t.y; sq += t.z * t.z; sq += t.w * t.w;
        }
        sq += __shfl_xor_sync(0xffffffffu, sq, 1);
        if (h == 0) zz_s[r] = sq;
    }
    __syncthreads();

    float zzv[8];
    #pragma unroll
    for (int i = 0; i < 8; i++) zzv[i] = zz_s[ty * 8 + i];

    float best[8];
    int   bidx[8];
    #pragma unroll
    for (int i = 0; i < 8; i++) { best[i] = 3.4e38f; bidx[i] = 0; }

    for (int ct = 0; ct < 8; ct++) {
        // ---- load codebook tile transposed + row sumsq ----
        {
            int r = tid >> 1, h = tid & 1;
            const float4* cp = reinterpret_cast<const float4*>(
                codebook + (size_t)(ct * 128 + r) * CODE_DIM) + h * 8;
            float sq = 0.0f;
            #pragma unroll
            for (int v = 0; v < 8; v++) {
                float4 t = cp[v];
                int k = h * 32 + v * 4;
                csT[(k + 0) * 128 + r] = t.x;
                csT[(k + 1) * 128 + r] = t.y;
                csT[(k + 2) * 128 + r] = t.z;
                csT[(k + 3) * 128 + r] = t.w;
                sq += t.x * t.x; sq += t.y * t.y; sq += t.z * t.z; sq += t.w * t.w;
            }
            sq += __shfl_xor_sync(0xffffffffu, sq, 1);
            if (h == 0) cc_s[r] = sq;
        }
        __syncthreads();

        float acc[8][8];
        #pragma unroll
        for (int i = 0; i < 8; i++)
            #pragma unroll
            for (int j = 0; j < 8; j++) acc[i][j] = 0.0f;

        #pragma unroll 8
        for (int k = 0; k < 64; k++) {
            float a[8], b[8];
            float4 a0 = *reinterpret_cast<const float4*>(&zsT[k * 128 + ty * 8]);
            float4 a1 = *reinterpret_cast<const float4*>(&zsT[k * 128 + ty * 8 + 4]);
            float4 b0 = *reinterpret_cast<const float4*>(&csT[k * 128 + tx * 8]);
            float4 b1 = *reinterpret_cast<const float4*>(&csT[k * 128 + tx * 8 + 4]);
            a[0] = a0.x; a[1] = a0.y; a[2] = a0.z; a[3] = a0.w;
            a[4] = a1.x; a[5] = a1.y; a[6] = a1.z; a[7] = a1.w;
            b[0] = b0.x; b[1] = b0.y; b[2] = b0.z; b[3] = b0.w;
            b[4] = b1.x; b[5] = b1.y; b[6] = b1.z; b[7] = b1.w;
            #pragma unroll
            for (int i = 0; i < 8; i++)
                #pragma unroll
                for (int j = 0; j < 8; j++)
                    acc[i][j] += a[i] * b[j];
        }

        // d2 = (zz - 2*dot) + cc, matching reference rounding order.
        // Codes scanned in ascending index order; strict < keeps the earliest (argmin tie rule).
        #pragma unroll
        for (int j = 0; j < 8; j++) {
            float cc = cc_s[tx * 8 + j];
            int code = ct * 128 + tx * 8 + j;
            #pragma unroll
            for (int i = 0; i < 8; i++) {
                float d2 = (zzv[i] - 2.0f * acc[i][j]) + cc;
                if (d2 < best[i]) { best[i] = d2; bidx[i] = code; }
            }
        }
        __syncthreads();   // before next tile overwrites csT/cc_s
    }

    // ---- cross-thread (tx) argmin reduction per token ----
    #pragma unroll
    for (int i = 0; i < 8; i++) {
        red_d[(ty * 8 + i) * 16 + tx] = best[i];
        red_i[(ty * 8 + i) * 16 + tx] = bidx[i];
    }
    __syncthreads();

    float lsum = 0.0f;
    if (tid < 128) {
        int t = tid;
        float bd = red_d[t * 16];
        int   bi = red_i[t * 16];
        #pragma unroll
        for (int j = 1; j < 16; j++) {
            float d = red_d[t * 16 + j];
            int  ix = red_i[t * 16 + j];
            if (d < bd || (d == bd && ix < bi)) { bd = d; bi = ix; }
        }
        int token = token0 + t;
        out_idx[token] = (float)bi;
        atomicAdd(&g_counts[bi], 1.0f);

        const float4* cb = reinterpret_cast<const float4*>(codebook + (size_t)bi * CODE_DIM);
        float4* qo = reinterpret_cast<float4*>(out_q + (size_t)token * CODE_DIM);
        #pragma unroll
        for (int v = 0; v < 16; v++) {
            float4 q = cb[v];
            int k = v * 4;
            float z0 = zsT[(k + 0) * 128 + t];
            float z1 = zsT[(k + 1) * 128 + t];
            float z2 = zsT[(k + 2) * 128 + t];
            float z3 = zsT[(k + 3) * 128 + t];
            float d0 = z0 - q.x, d1 = z1 - q.y, d2 = z2 - q.z, d3 = z3 - q.w;
            lsum += d0 * d0; lsum += d1 * d1; lsum += d2 * d2; lsum += d3 * d3;
            qo[v] = q;
            atomicAdd(&g_dw[bi * CODE_DIM + k + 0], z0);
            atomicAdd(&g_dw[bi * CODE_DIM + k + 1], z1);
            atomicAdd(&g_dw[bi * CODE_DIM + k + 2], z2);
            atomicAdd(&g_dw[bi * CODE_DIM + k + 3], z3);
        }
    }

    // ---- block reduction of commitment-loss partial (all 256 threads) ----
    #pragma unroll
    for (int o = 16; o > 0; o >>= 1) lsum += __shfl_down_sync(0xffffffffu, lsum, o);
    __shared__ float lpart[8];
    if ((tid & 31) == 0) lpart[tid >> 5] = lsum;
    __syncthreads();
    if (tid == 0) {
        float s = 0.0f;
        #pragma unroll
        for (int w = 0; w < 8; w++) s += lpart[w];
        atomicAdd(&g_loss, s);
    }
}

// ---------------- finalize 1: new_cluster_size + its sum ----------------
__global__ void vq_final_cs(const float* __restrict__ cluster_size,
                            float* __restrict__ out_cs)
{
    int t = threadIdx.x;  // 1024 threads, 1 block
    float ncs = 0.99f * cluster_size[t] + 0.01f * g_counts[t];
    out_cs[t] = ncs;
    g_ncs[t] = ncs;

    float s = ncs;
    #pragma unroll
    for (int o = 16; o > 0; o >>= 1) s += __shfl_down_sync(0xffffffffu, s, o);
    __shared__ float p[32];
    if ((t & 31) == 0) p[t >> 5] = s;
    __syncthreads();
    if (t < 32) {
        float v = p[t];
        #pragma unroll
        for (int o = 16; o > 0; o >>= 1) v += __shfl_down_sync(0xffffffffu, v, o);
        if (t == 0) g_n = v;
    }
}

// ---------------- finalize 2: new_ema_w, new_codebook, loss ----------------
__global__ void vq_final_cb(const float* __restrict__ ema_w,
                            float* __restrict__ out_ew,
                            float* __restrict__ out_cb,
                            float* __restrict__ out_loss)
{
    int i = blockIdx.x * blockDim.x + threadIdx.x;  // 65536
    float e = 0.99f * ema_w[i] + 0.01f * g_dw[i];
    out_ew[i] = e;
    int k = i >> 6;
    float n = g_n;
    float cs = (g_ncs[k] + 1e-5f) / (n + 1024.0f * 1e-5f) * n;
    out_cb[i] = e / cs;
    if (i == 0) out_loss[0] = g_loss * (1.0f / 8388608.0f);  // 2^-23, exact == /(N*D)
}

// ---------------- launch ----------------
extern "C" void kernel_launch(void* const* d_in, const int* in_sizes, int n_in,
                              void* d_out, int out_size)
{
    const float* z            = (const float*)d_in[0];
    const float* codebook     = (const float*)d_in[1];
    const float* cluster_size = (const float*)d_in[2];
    const float* ema_w        = (const float*)d_in[3];
    float* out = (float*)d_out;

    // output packing: quantized_st | indices | loss | new_codebook | new_cluster_size | new_ema_w
    const size_t OFF_Q    = 0;
    const size_t OFF_IDX  = (size_t)N_TOKENS * CODE_DIM;          // 8388608
    const size_t OFF_LOSS = OFF_IDX + N_TOKENS;                   // 8519680
    const size_t OFF_CB   = OFF_LOSS + 1;                         // 8519681
    const size_t OFF_CS   = OFF_CB + NUM_CODES * CODE_DIM;        // 8585217
    const size_t OFF_EW   = OFF_CS + NUM_CODES;                   // 8586241

    const int smem_bytes = (8192 + 8192 + 128 + 128 + 2048 + 2048) * 4;  // 82944
    cudaFuncSetAttribute(vq_main, cudaFuncAttributeMaxDynamicSharedMemorySize, smem_bytes);

    vq_zero<<<(NUM_CODES * CODE_DIM + 255) / 256, 256>>>();
    vq_main<<<N_TOKENS / 128, 256, smem_bytes>>>(z, codebook, out + OFF_Q, out + OFF_IDX);
    vq_final_cs<<<1, NUM_CODES>>>(cluster_size, out + OFF_CS);
    vq_final_cb<<<(NUM_CODES * CODE_DIM) / 256, 256>>>(ema_w, out + OFF_EW,
                                                       out + OFF_CB, out + OFF_LOSS);
}